// round 12
// baseline (speedup 1.0000x reference)
#include <cuda_runtime.h>
#include <cuda_fp16.h>
#include <math.h>
#include <stdint.h>
#include <mma.h>

using namespace nvcuda;

#define BS    4096
#define NSLOT 32
#define D     256

// Packed fp16 scratch: [batch][tensor(q,k,v)][slot][dim]
#define BSTRIDE (3 * NSLOT * D)     // 24576 halfs per batch
__device__ __align__(16) __half g_scr[(size_t)BS * BSTRIDE];
__device__ __align__(16) __half g_wh [(size_t)96 * D * D];    // fp16 weights [gemm][k][n]
__device__ __align__(16) __half g_xh [(size_t)64 * BS * D];   // fp16 inputs: 0-31 q, 32-63 k

__device__ __forceinline__ uint32_t smem_u32(const void* p) {
    return (uint32_t)__cvta_generic_to_shared(p);
}
#define CP_ASYNC16(dst_u32, src_ptr) \
    asm volatile("cp.async.cg.shared.global [%0], [%1], 16;" :: "r"(dst_u32), "l"(src_ptr))
#define CP_COMMIT() asm volatile("cp.async.commit_group;" ::: "memory")
#define CP_WAIT0()  asm volatile("cp.async.wait_group 0;" ::: "memory")

// ---------------------------------------------------------------------------
// Phase 0a: weights fp32 -> fp16 in proj gemm order.
// ---------------------------------------------------------------------------
__global__ __launch_bounds__(256) void convert_w(
    const float* __restrict__ qw,
    const float* __restrict__ kw,
    const float* __restrict__ vw)
{
    const int y = blockIdx.y;
    const float* W;
    if (y < 32) W = qw + (size_t)y * D * D;
    else {
        const int s = (y - 32) >> 1;
        W = (((y - 32) & 1) == 0 ? kw : vw) + (size_t)s * D * D;
    }
    __half* dst = g_wh + (size_t)y * D * D;
    const int base = (blockIdx.x * 256 + threadIdx.x) * 4;
#pragma unroll
    for (int p = 0; p < 4; p++) {
        const int i = base + p * 16384;
        const float4 v = *(const float4*)&W[i];
        __half2 h0 = __floats2half2_rn(v.x, v.y);
        __half2 h1 = __floats2half2_rn(v.z, v.w);
        *(uint2*)&dst[i] = make_uint2(*(uint32_t*)&h0, *(uint32_t*)&h1);
    }
}

// ---------------------------------------------------------------------------
// Phase 0b: inputs fp32 -> fp16. y<32: q[y]; y>=32: k[y-32].
// grid (512, 64), 8 floats per thread.
// ---------------------------------------------------------------------------
__global__ __launch_bounds__(256) void convert_x(
    const float* __restrict__ q,
    const float* __restrict__ k)
{
    const int y = blockIdx.y;
    const float* X = (y < 32) ? (q + (size_t)y * BS * D)
                              : (k + (size_t)(y - 32) * BS * D);
    __half* dst = g_xh + (size_t)y * BS * D;
    const int i = (blockIdx.x * 256 + threadIdx.x) * 8;
    const float4 v0 = *(const float4*)&X[i];
    const float4 v1 = *(const float4*)&X[i + 4];
    __half2 h0 = __floats2half2_rn(v0.x, v0.y);
    __half2 h1 = __floats2half2_rn(v0.z, v0.w);
    __half2 h2 = __floats2half2_rn(v1.x, v1.y);
    __half2 h3 = __floats2half2_rn(v1.z, v1.w);
    *(uint4*)&dst[i] = make_uint4(*(uint32_t*)&h0, *(uint32_t*)&h1,
                                  *(uint32_t*)&h2, *(uint32_t*)&h3);
}

// ---------------------------------------------------------------------------
// Phase 1: 96 GEMMs C[4096,256] = X @ W, fp16 HMMA. Round-7 mainloop, but
// A and B both staged via cp.async from pre-converted fp16 (pure copies).
// grid (2,32,96), block 256 (8 warps 2m x 4n), tile 128x128, K-chunk 32,
// double-buffered, 2 CTAs/SM.
// ---------------------------------------------------------------------------
#define A_LD  40
#define B_LD  136
#define ASZ   (128 * A_LD)
#define BSZ   (32 * B_LD)
#define STG   (ASZ + BSZ)
#define PROJ_SMEM_BYTES (2 * STG * (int)sizeof(__half))   // 37888 B

__global__ __launch_bounds__(256, 2) void proj_wmma()
{
    extern __shared__ __align__(16) __half smh[];
    const uint32_t smb = smem_u32(smh);

    const int tid  = threadIdx.x;
    const int wid  = tid >> 5;
    const int lane = tid & 31;
    const int wm   = wid >> 2;
    const int wn   = wid & 3;
    const int n0   = blockIdx.x * 128;
    const int m0   = blockIdx.y * 128;
    const int y    = blockIdx.z;

    int t_idx, s_idx, xi;
    if (y < 32) { t_idx = 0; s_idx = y; xi = y; }
    else {
        s_idx = (y - 32) >> 1;
        t_idx = (((y - 32) & 1) == 0) ? 1 : 2;
        xi = 32 + s_idx;
    }
    const __half* X = g_xh + (size_t)xi * BS * D;
    const __half* W = g_wh + (size_t)y * D * D;
    __half* C = g_scr + (size_t)t_idx * (NSLOT * D) + (size_t)s_idx * D;

    // A: 128 rows x 32 halfs = 512 16B segs (2/thread)
    // B: 32 rows x 128 halfs = 512 16B segs (2/thread)
    auto issueAB = [&](int c, int buf) {
#pragma unroll
        for (int p = 0; p < 2; p++) {
            const int idx  = p * 256 + tid;
            const int arow = idx >> 2;
            const int ac8  = (idx & 3) * 8;
            CP_ASYNC16(smb + (buf * STG + arow * A_LD + ac8) * 2,
                       X + (size_t)(m0 + arow) * D + c * 32 + ac8);
        }
#pragma unroll
        for (int p = 0; p < 2; p++) {
            const int idx  = p * 256 + tid;
            const int brow = idx >> 4;
            const int bc8  = (idx & 15) * 8;
            CP_ASYNC16(smb + (buf * STG + ASZ + brow * B_LD + bc8) * 2,
                       W + (size_t)(c * 32 + brow) * D + n0 + bc8);
        }
        CP_COMMIT();
    };

    wmma::fragment<wmma::accumulator, 16, 16, 16, float> cf[4][2];
#pragma unroll
    for (int i = 0; i < 4; i++)
#pragma unroll
        for (int j = 0; j < 2; j++) wmma::fill_fragment(cf[i][j], 0.0f);

    issueAB(0, 0);
    CP_WAIT0();
    __syncthreads();

    for (int c = 0; c < 8; c++) {
        const int buf = c & 1;
        if (c < 7) issueAB(c + 1, buf ^ 1);

        const __half* a_s = smh + buf * STG;
        const __half* b_s = a_s + ASZ;
#pragma unroll
        for (int ks = 0; ks < 2; ks++) {
            wmma::fragment<wmma::matrix_a, 16, 16, 16, __half, wmma::row_major> af[4];
            wmma::fragment<wmma::matrix_b, 16, 16, 16, __half, wmma::row_major> bf[2];
#pragma unroll
            for (int i = 0; i < 4; i++)
                wmma::load_matrix_sync(af[i], a_s + (wm * 64 + 16 * i) * A_LD + ks * 16, A_LD);
#pragma unroll
            for (int j = 0; j < 2; j++)
                wmma::load_matrix_sync(bf[j], b_s + (ks * 16) * B_LD + wn * 32 + 16 * j, B_LD);
#pragma unroll
            for (int i = 0; i < 4; i++)
#pragma unroll
                for (int j = 0; j < 2; j++)
                    wmma::mma_sync(cf[i][j], af[i], bf[j], cf[i][j]);
        }

        if (c < 7) CP_WAIT0();
        __syncthreads();
    }

    // Epilogue -> packed scratch
    float* stg = reinterpret_cast<float*>(smh) + wid * (16 * 20);
    const int er = lane >> 1;
    const int ec = (lane & 1) * 8;
#pragma unroll
    for (int i = 0; i < 4; i++) {
#pragma unroll
        for (int j = 0; j < 2; j++) {
            wmma::store_matrix_sync(stg, cf[i][j], 20, wmma::mem_row_major);
            __syncwarp();
            __half2 h[4];
#pragma unroll
            for (int t = 0; t < 4; t++)
                h[t] = __floats2half2_rn(stg[er * 20 + ec + 2 * t], stg[er * 20 + ec + 2 * t + 1]);
            const int brow = m0 + wm * 64 + 16 * i + er;
            *(uint4*)&C[(size_t)brow * BSTRIDE + n0 + wn * 32 + 16 * j + ec] = *(uint4*)&h[0];
            __syncwarp();
        }
    }
}

// ---------------------------------------------------------------------------
// Phase 2: per-batch attention (round-10/11 version, 53us).
// ---------------------------------------------------------------------------
#define QK_LD 264
#define LG_LD 36
#define P_LD  40
#define ATTN_SMEM_BYTES ((3 * 32 * QK_LD) * 2 + (32 * LG_LD) * 4 + (32 * P_LD) * 2)  // 57856

__global__ __launch_bounds__(256, 4) void attn_tc(float* __restrict__ out)
{
    extern __shared__ __align__(16) __half smem_h[];
    __half* qh = smem_h;
    __half* kh = qh + 32 * QK_LD;
    __half* vh = kh + 32 * QK_LD;
    float*  lg = (float*)(vh + 32 * QK_LD);
    __half* ph = (__half*)(lg + 32 * LG_LD);

    const int b   = blockIdx.x;
    const int tid = threadIdx.x;
    const int wid = tid >> 5;
    const uint32_t sb0 = smem_u32(qh);
    const __half* src = g_scr + (size_t)b * BSTRIDE;

#pragma unroll
    for (int p = 0; p < 12; p++) {
        const int idx = p * 256 + tid;
        const int t   = idx >> 10;
        const int rem = idx & 1023;
        const int n   = rem >> 5;
        const int a8  = (rem & 31) * 8;
        const uint32_t dst = sb0 + (t * 32 * QK_LD + n * QK_LD + a8) * 2;
        CP_ASYNC16(dst, src + idx * 8);
    }
    CP_COMMIT();
    CP_WAIT0();
    __syncthreads();

    if (wid < 4) {
        const int nt = wid >> 1;
        const int mt = wid & 1;
        wmma::fragment<wmma::accumulator, 16, 16, 16, float> acc;
        wmma::fill_fragment(acc, 0.0f);
#pragma unroll
        for (int ks = 0; ks < 16; ks++) {
            wmma::fragment<wmma::matrix_a, 16, 16, 16, __half, wmma::row_major> af;
            wmma::fragment<wmma::matrix_b, 16, 16, 16, __half, wmma::col_major> bf;
            wmma::load_matrix_sync(af, qh + (nt * 16) * QK_LD + ks * 16, QK_LD);
            wmma::load_matrix_sync(bf, kh + (mt * 16) * QK_LD + ks * 16, QK_LD);
            wmma::mma_sync(acc, af, bf, acc);
        }
        wmma::store_matrix_sync(lg + (nt * 16) * LG_LD + mt * 16, acc, LG_LD,
                                wmma::mem_row_major);
    }
    __syncthreads();

    {
        const int row = tid >> 3;
        const int c0  = (tid & 7) * 4;
        float x0 = lg[row * LG_LD + c0 + 0];
        float x1 = lg[row * LG_LD + c0 + 1];
        float x2 = lg[row * LG_LD + c0 + 2];
        float x3 = lg[row * LG_LD + c0 + 3];
        float mx = fmaxf(fmaxf(x0, x1), fmaxf(x2, x3));
#pragma unroll
        for (int d = 1; d < 8; d <<= 1)
            mx = fmaxf(mx, __shfl_xor_sync(0xffffffffu, mx, d));
        x0 = expf((x0 - mx) * 0.0625f);
        x1 = expf((x1 - mx) * 0.0625f);
        x2 = expf((x2 - mx) * 0.0625f);
        x3 = expf((x3 - mx) * 0.0625f);
        float s = x0 + x1 + x2 + x3;
#pragma unroll
        for (int d = 1; d < 8; d <<= 1)
            s += __shfl_xor_sync(0xffffffffu, s, d);
        const float inv = 1.0f / s;
        __half2 h0 = __floats2half2_rn(x0 * inv, x1 * inv);
        __half2 h1 = __floats2half2_rn(x2 * inv, x3 * inv);
        *(uint2*)&ph[row * P_LD + c0] = make_uint2(*(uint32_t*)&h0, *(uint32_t*)&h1);
    }
    __syncthreads();

    {
        const int mt2 = wid >> 2;
        const int oc  = wid & 3;
        wmma::fragment<wmma::accumulator, 16, 16, 16, float> acc[4];
#pragma unroll
        for (int j = 0; j < 4; j++) wmma::fill_fragment(acc[j], 0.0f);
#pragma unroll
        for (int ks = 0; ks < 2; ks++) {
            wmma::fragment<wmma::matrix_a, 16, 16, 16, __half, wmma::row_major> af;
            wmma::load_matrix_sync(af, ph + (mt2 * 16) * P_LD + ks * 16, P_LD);
#pragma unroll
            for (int j = 0; j < 4; j++) {
                wmma::fragment<wmma::matrix_b, 16, 16, 16, __half, wmma::row_major> bf;
                wmma::load_matrix_sync(bf, vh + (ks * 16) * QK_LD + oc * 64 + j * 16, QK_LD);
                wmma::mma_sync(acc[j], af, bf, acc[j]);
            }
        }
#pragma unroll
        for (int j = 0; j < 4; j++) {
            float* dst = out + (size_t)(mt2 * 16) * BS * D + (size_t)b * D + oc * 64 + j * 16;
            wmma::store_matrix_sync(dst, acc[j], (unsigned)(BS * D), wmma::mem_row_major);
        }
    }
}

// ---------------------------------------------------------------------------
extern "C" void kernel_launch(void* const* d_in, const int* in_sizes, int n_in,
                              void* d_out, int out_size)
{
    const float* q  = (const float*)d_in[0];
    const float* k  = (const float*)d_in[1];
    const float* qw = (const float*)d_in[2];
    const float* kw = (const float*)d_in[3];
    const float* vw = (const float*)d_in[4];
    float* out = (float*)d_out;

    (void)in_sizes; (void)n_in; (void)out_size;

    dim3 gw(16, 96);
    convert_w<<<gw, 256>>>(qw, kw, vw);
    dim3 gx(512, 64);
    convert_x<<<gx, 256>>>(q, k);

    cudaFuncSetAttribute(proj_wmma, cudaFuncAttributeMaxDynamicSharedMemorySize, PROJ_SMEM_BYTES);
    dim3 grid1(2, 32, 96);
    proj_wmma<<<grid1, 256, PROJ_SMEM_BYTES>>>();

    cudaFuncSetAttribute(attn_tc, cudaFuncAttributeMaxDynamicSharedMemorySize, ATTN_SMEM_BYTES);
    attn_tc<<<BS, 256, ATTN_SMEM_BYTES>>>(out);
}

// round 13
// speedup vs baseline: 1.0521x; 1.0521x over previous
#include <cuda_runtime.h>
#include <cuda_fp16.h>
#include <math.h>
#include <stdint.h>
#include <mma.h>

using namespace nvcuda;

#define BS    4096
#define NSLOT 32
#define D     256

// Packed fp16 scratch: [batch][tensor(q,k,v)][slot][dim]
#define BSTRIDE (3 * NSLOT * D)     // 24576 halfs per batch
__device__ __align__(16) __half g_scr[(size_t)BS * BSTRIDE];
__device__ __align__(16) __half g_wh [(size_t)96 * D * D];   // fp16 weights [gemm][k][n]

__device__ __forceinline__ uint32_t smem_u32(const void* p) {
    return (uint32_t)__cvta_generic_to_shared(p);
}
#define CP_ASYNC16(dst_u32, src_ptr) \
    asm volatile("cp.async.cg.shared.global [%0], [%1], 16;" :: "r"(dst_u32), "l"(src_ptr))
#define CP_COMMIT() asm volatile("cp.async.commit_group;" ::: "memory")
#define CP_WAIT0()  asm volatile("cp.async.wait_group 0;" ::: "memory")

// ---------------------------------------------------------------------------
// Phase 0: weights fp32 -> fp16 in proj gemm order:
//   y < 32 -> qw[y];  y >= 32 -> s=(y-32)>>1, even->kw[s], odd->vw[s]
// ---------------------------------------------------------------------------
__global__ __launch_bounds__(256) void convert_w(
    const float* __restrict__ qw,
    const float* __restrict__ kw,
    const float* __restrict__ vw)
{
    const int y = blockIdx.y;
    const float* W;
    if (y < 32) W = qw + (size_t)y * D * D;
    else {
        const int s = (y - 32) >> 1;
        W = (((y - 32) & 1) == 0 ? kw : vw) + (size_t)s * D * D;
    }
    __half* dst = g_wh + (size_t)y * D * D;
    const int base = (blockIdx.x * 256 + threadIdx.x) * 4;
#pragma unroll
    for (int p = 0; p < 4; p++) {
        const int i = base + p * 16384;
        const float4 v = *(const float4*)&W[i];
        __half2 h0 = __floats2half2_rn(v.x, v.y);
        __half2 h1 = __floats2half2_rn(v.z, v.w);
        *(uint2*)&dst[i] = make_uint2(*(uint32_t*)&h0, *(uint32_t*)&h1);
    }
}

// ---------------------------------------------------------------------------
// Phase 1: 96 GEMMs C[4096,256] = X @ W, fp16 HMMA.
// Round-11 geometry: grid (2,32,96), block 256 (8 warps 2m x 4n), tile
// 128x128, K-chunk 32, 2 CTAs/SM. CHANGE: quad-buffered smem, sync every
// TWO chunks (8 -> 4 barriers), prefetch distance 2 chunks.
// ---------------------------------------------------------------------------
#define A_LD  40
#define B_LD  136
#define ASZ   (128 * A_LD)
#define BSZ   (32 * B_LD)
#define STG   (ASZ + BSZ)                  // 9472 halfs
#define PROJ_SMEM_BYTES (4 * STG * (int)sizeof(__half))   // 75776 B

__global__ __launch_bounds__(256, 2) void proj_wmma(
    const float* __restrict__ q,
    const float* __restrict__ k)
{
    extern __shared__ __align__(16) __half smh[];

    const int tid  = threadIdx.x;
    const int wid  = tid >> 5;
    const int lane = tid & 31;
    const int wm   = wid >> 2;
    const int wn   = wid & 3;
    const int n0   = blockIdx.x * 128;
    const int m0   = blockIdx.y * 128;
    const int y    = blockIdx.z;

    const float* X;
    int t_idx, s_idx;
    if (y < 32) { X = q + (size_t)y * BS * D; t_idx = 0; s_idx = y; }
    else {
        s_idx = (y - 32) >> 1;
        X = k + (size_t)s_idx * BS * D;
        t_idx = (((y - 32) & 1) == 0) ? 1 : 2;
    }
    __half* C = g_scr + (size_t)t_idx * (NSLOT * D) + (size_t)s_idx * D;
    const __half* W = g_wh + (size_t)y * D * D;

    const int a_row = tid >> 3;
    const int a_c4  = (tid & 7) * 4;
    const int b_kk  = tid >> 4;
    const int b_n8  = (tid & 15) * 8;

    float4 ra[4];
    uint4  rb[2];

    auto load_regs = [&](int c) {
#pragma unroll
        for (int p = 0; p < 4; p++)
            ra[p] = *(const float4*)&X[(size_t)(m0 + a_row + 32 * p) * D + c * 32 + a_c4];
#pragma unroll
        for (int p = 0; p < 2; p++)
            rb[p] = *(const uint4*)&W[(size_t)(c * 32 + b_kk + 16 * p) * D + n0 + b_n8];
    };
    auto store_smem = [&](int buf) {
        __half* a_s = smh + buf * STG;
        __half* b_s = a_s + ASZ;
#pragma unroll
        for (int p = 0; p < 4; p++) {
            __half2 h0 = __floats2half2_rn(ra[p].x, ra[p].y);
            __half2 h1 = __floats2half2_rn(ra[p].z, ra[p].w);
            *(__half2*)&a_s[(a_row + 32 * p) * A_LD + a_c4]     = h0;
            *(__half2*)&a_s[(a_row + 32 * p) * A_LD + a_c4 + 2] = h1;
        }
#pragma unroll
        for (int p = 0; p < 2; p++)
            *(uint4*)&b_s[(b_kk + 16 * p) * B_LD + b_n8] = rb[p];
    };

    wmma::fragment<wmma::accumulator, 16, 16, 16, float> cf[4][2];
#pragma unroll
    for (int i = 0; i < 4; i++)
#pragma unroll
        for (int j = 0; j < 2; j++) wmma::fill_fragment(cf[i][j], 0.0f);

    auto mma_chunk = [&](int buf) {
        const __half* a_s = smh + buf * STG;
        const __half* b_s = a_s + ASZ;
#pragma unroll
        for (int ks = 0; ks < 2; ks++) {
            wmma::fragment<wmma::matrix_a, 16, 16, 16, __half, wmma::row_major> af[4];
            wmma::fragment<wmma::matrix_b, 16, 16, 16, __half, wmma::row_major> bf[2];
#pragma unroll
            for (int i = 0; i < 4; i++)
                wmma::load_matrix_sync(af[i], a_s + (wm * 64 + 16 * i) * A_LD + ks * 16, A_LD);
#pragma unroll
            for (int j = 0; j < 2; j++)
                wmma::load_matrix_sync(bf[j], b_s + (ks * 16) * B_LD + wn * 32 + 16 * j, B_LD);
#pragma unroll
            for (int i = 0; i < 4; i++)
#pragma unroll
                for (int j = 0; j < 2; j++)
                    wmma::mma_sync(cf[i][j], af[i], bf[j], cf[i][j]);
        }
    };

    // Prologue: chunks 0,1 -> bufs 0,1
    load_regs(0); store_smem(0);
    load_regs(1); store_smem(1);
    __syncthreads();

    // 4 iterations of 2 chunks; one barrier per iteration
#pragma unroll
    for (int cc = 0; cc < 4; cc++) {
        const int c0 = 2 * cc;
        if (cc < 3) load_regs(c0 + 2);
        mma_chunk(c0 & 3);
        if (cc < 3) { store_smem((c0 + 2) & 3); load_regs(c0 + 3); }
        mma_chunk((c0 + 1) & 3);
        if (cc < 3) store_smem((c0 + 3) & 3);
        __syncthreads();
    }

    // Epilogue -> packed scratch
    float* stg = reinterpret_cast<float*>(smh) + wid * (16 * 20);
    const int er = lane >> 1;
    const int ec = (lane & 1) * 8;
#pragma unroll
    for (int i = 0; i < 4; i++) {
#pragma unroll
        for (int j = 0; j < 2; j++) {
            wmma::store_matrix_sync(stg, cf[i][j], 20, wmma::mem_row_major);
            __syncwarp();
            __half2 h[4];
#pragma unroll
            for (int t = 0; t < 4; t++)
                h[t] = __floats2half2_rn(stg[er * 20 + ec + 2 * t], stg[er * 20 + ec + 2 * t + 1]);
            const int brow = m0 + wm * 64 + 16 * i + er;
            *(uint4*)&C[(size_t)brow * BSTRIDE + n0 + wn * 32 + 16 * j + ec] = *(uint4*)&h[0];
            __syncwarp();
        }
    }
}

// ---------------------------------------------------------------------------
// Phase 2: per-batch attention (round-10/11 version, 53us).
// ---------------------------------------------------------------------------
#define QK_LD 264
#define LG_LD 36
#define P_LD  40
#define ATTN_SMEM_BYTES ((3 * 32 * QK_LD) * 2 + (32 * LG_LD) * 4 + (32 * P_LD) * 2)  // 57856

__global__ __launch_bounds__(256, 4) void attn_tc(float* __restrict__ out)
{
    extern __shared__ __align__(16) __half smem_h[];
    __half* qh = smem_h;
    __half* kh = qh + 32 * QK_LD;
    __half* vh = kh + 32 * QK_LD;
    float*  lg = (float*)(vh + 32 * QK_LD);
    __half* ph = (__half*)(lg + 32 * LG_LD);

    const int b   = blockIdx.x;
    const int tid = threadIdx.x;
    const int wid = tid >> 5;
    const uint32_t sb0 = smem_u32(qh);
    const __half* src = g_scr + (size_t)b * BSTRIDE;

#pragma unroll
    for (int p = 0; p < 12; p++) {
        const int idx = p * 256 + tid;
        const int t   = idx >> 10;
        const int rem = idx & 1023;
        const int n   = rem >> 5;
        const int a8  = (rem & 31) * 8;
        const uint32_t dst = sb0 + (t * 32 * QK_LD + n * QK_LD + a8) * 2;
        CP_ASYNC16(dst, src + idx * 8);
    }
    CP_COMMIT();
    CP_WAIT0();
    __syncthreads();

    if (wid < 4) {
        const int nt = wid >> 1;
        const int mt = wid & 1;
        wmma::fragment<wmma::accumulator, 16, 16, 16, float> acc;
        wmma::fill_fragment(acc, 0.0f);
#pragma unroll
        for (int ks = 0; ks < 16; ks++) {
            wmma::fragment<wmma::matrix_a, 16, 16, 16, __half, wmma::row_major> af;
            wmma::fragment<wmma::matrix_b, 16, 16, 16, __half, wmma::col_major> bf;
            wmma::load_matrix_sync(af, qh + (nt * 16) * QK_LD + ks * 16, QK_LD);
            wmma::load_matrix_sync(bf, kh + (mt * 16) * QK_LD + ks * 16, QK_LD);
            wmma::mma_sync(acc, af, bf, acc);
        }
        wmma::store_matrix_sync(lg + (nt * 16) * LG_LD + mt * 16, acc, LG_LD,
                                wmma::mem_row_major);
    }
    __syncthreads();

    {
        const int row = tid >> 3;
        const int c0  = (tid & 7) * 4;
        float x0 = lg[row * LG_LD + c0 + 0];
        float x1 = lg[row * LG_LD + c0 + 1];
        float x2 = lg[row * LG_LD + c0 + 2];
        float x3 = lg[row * LG_LD + c0 + 3];
        float mx = fmaxf(fmaxf(x0, x1), fmaxf(x2, x3));
#pragma unroll
        for (int d = 1; d < 8; d <<= 1)
            mx = fmaxf(mx, __shfl_xor_sync(0xffffffffu, mx, d));
        x0 = expf((x0 - mx) * 0.0625f);
        x1 = expf((x1 - mx) * 0.0625f);
        x2 = expf((x2 - mx) * 0.0625f);
        x3 = expf((x3 - mx) * 0.0625f);
        float s = x0 + x1 + x2 + x3;
#pragma unroll
        for (int d = 1; d < 8; d <<= 1)
            s += __shfl_xor_sync(0xffffffffu, s, d);
        const float inv = 1.0f / s;
        __half2 h0 = __floats2half2_rn(x0 * inv, x1 * inv);
        __half2 h1 = __floats2half2_rn(x2 * inv, x3 * inv);
        *(uint2*)&ph[row * P_LD + c0] = make_uint2(*(uint32_t*)&h0, *(uint32_t*)&h1);
    }
    __syncthreads();

    {
        const int mt2 = wid >> 2;
        const int oc  = wid & 3;
        wmma::fragment<wmma::accumulator, 16, 16, 16, float> acc[4];
#pragma unroll
        for (int j = 0; j < 4; j++) wmma::fill_fragment(acc[j], 0.0f);
#pragma unroll
        for (int ks = 0; ks < 2; ks++) {
            wmma::fragment<wmma::matrix_a, 16, 16, 16, __half, wmma::row_major> af;
            wmma::load_matrix_sync(af, ph + (mt2 * 16) * P_LD + ks * 16, P_LD);
#pragma unroll
            for (int j = 0; j < 4; j++) {
                wmma::fragment<wmma::matrix_b, 16, 16, 16, __half, wmma::row_major> bf;
                wmma::load_matrix_sync(bf, vh + (ks * 16) * QK_LD + oc * 64 + j * 16, QK_LD);
                wmma::mma_sync(acc[j], af, bf, acc[j]);
            }
        }
#pragma unroll
        for (int j = 0; j < 4; j++) {
            float* dst = out + (size_t)(mt2 * 16) * BS * D + (size_t)b * D + oc * 64 + j * 16;
            wmma::store_matrix_sync(dst, acc[j], (unsigned)(BS * D), wmma::mem_row_major);
        }
    }
}

// ---------------------------------------------------------------------------
extern "C" void kernel_launch(void* const* d_in, const int* in_sizes, int n_in,
                              void* d_out, int out_size)
{
    const float* q  = (const float*)d_in[0];
    const float* k  = (const float*)d_in[1];
    const float* qw = (const float*)d_in[2];
    const float* kw = (const float*)d_in[3];
    const float* vw = (const float*)d_in[4];
    float* out = (float*)d_out;

    (void)in_sizes; (void)n_in; (void)out_size;

    dim3 gw(16, 96);
    convert_w<<<gw, 256>>>(qw, kw, vw);

    cudaFuncSetAttribute(proj_wmma, cudaFuncAttributeMaxDynamicSharedMemorySize, PROJ_SMEM_BYTES);
    dim3 grid1(2, 32, 96);
    proj_wmma<<<grid1, 256, PROJ_SMEM_BYTES>>>(q, k);

    cudaFuncSetAttribute(attn_tc, cudaFuncAttributeMaxDynamicSharedMemorySize, ATTN_SMEM_BYTES);
    attn_tc<<<BS, 256, ATTN_SMEM_BYTES>>>(out);
}

// round 14
// speedup vs baseline: 1.1104x; 1.0555x over previous
#include <cuda_runtime.h>
#include <cuda_fp16.h>
#include <math.h>
#include <stdint.h>
#include <mma.h>

using namespace nvcuda;

#define BS    4096
#define NSLOT 32
#define D     256

// Packed fp16 scratch: [batch][tensor(q,k,v)][slot][dim]
#define BSTRIDE (3 * NSLOT * D)     // 24576 halfs per batch
__device__ __align__(16) __half g_scr[(size_t)BS * BSTRIDE];
__device__ __align__(16) __half g_wh [(size_t)96 * D * D];   // fp16 weights [gemm][k][n]

__device__ __forceinline__ uint32_t smem_u32(const void* p) {
    return (uint32_t)__cvta_generic_to_shared(p);
}
#define CP_ASYNC16(dst_u32, src_ptr) \
    asm volatile("cp.async.cg.shared.global [%0], [%1], 16;" :: "r"(dst_u32), "l"(src_ptr))
#define CP_COMMIT() asm volatile("cp.async.commit_group;" ::: "memory")
#define CP_WAIT0()  asm volatile("cp.async.wait_group 0;" ::: "memory")

// ---------------------------------------------------------------------------
// Phase 0: weights fp32 -> fp16 in proj gemm order:
//   y < 32 -> qw[y];  y >= 32 -> s=(y-32)>>1, even->kw[s], odd->vw[s]
// ---------------------------------------------------------------------------
__global__ __launch_bounds__(256) void convert_w(
    const float* __restrict__ qw,
    const float* __restrict__ kw,
    const float* __restrict__ vw)
{
    const int y = blockIdx.y;
    const float* W;
    if (y < 32) W = qw + (size_t)y * D * D;
    else {
        const int s = (y - 32) >> 1;
        W = (((y - 32) & 1) == 0 ? kw : vw) + (size_t)s * D * D;
    }
    __half* dst = g_wh + (size_t)y * D * D;
    const int base = (blockIdx.x * 256 + threadIdx.x) * 4;
#pragma unroll
    for (int p = 0; p < 4; p++) {
        const int i = base + p * 16384;
        const float4 v = *(const float4*)&W[i];
        __half2 h0 = __floats2half2_rn(v.x, v.y);
        __half2 h1 = __floats2half2_rn(v.z, v.w);
        *(uint2*)&dst[i] = make_uint2(*(uint32_t*)&h0, *(uint32_t*)&h1);
    }
}

// ---------------------------------------------------------------------------
// Phase 1: 96 GEMMs C[4096,256] = X @ W, fp16 HMMA. (round-7/11 final form)
// grid (2,32,96), block 256 (8 warps 2m x 4n), tile 128x128, K-chunk 32,
// double-buffered, 2 CTAs/SM.
// ---------------------------------------------------------------------------
#define A_LD  40
#define B_LD  136
#define ASZ   (128 * A_LD)
#define BSZ   (32 * B_LD)
#define STG   (ASZ + BSZ)
#define PROJ_SMEM_BYTES (2 * STG * (int)sizeof(__half))   // 37888 B

__global__ __launch_bounds__(256, 2) void proj_wmma(
    const float* __restrict__ q,
    const float* __restrict__ k)
{
    extern __shared__ __align__(16) __half smh[];

    const int tid  = threadIdx.x;
    const int wid  = tid >> 5;
    const int lane = tid & 31;
    const int wm   = wid >> 2;
    const int wn   = wid & 3;
    const int n0   = blockIdx.x * 128;
    const int m0   = blockIdx.y * 128;
    const int y    = blockIdx.z;

    const float* X;
    int t_idx, s_idx;
    if (y < 32) { X = q + (size_t)y * BS * D; t_idx = 0; s_idx = y; }
    else {
        s_idx = (y - 32) >> 1;
        X = k + (size_t)s_idx * BS * D;
        t_idx = (((y - 32) & 1) == 0) ? 1 : 2;
    }
    __half* C = g_scr + (size_t)t_idx * (NSLOT * D) + (size_t)s_idx * D;
    const __half* W = g_wh + (size_t)y * D * D;

    const int a_row = tid >> 3;
    const int a_c4  = (tid & 7) * 4;
    const int b_kk  = tid >> 4;
    const int b_n8  = (tid & 15) * 8;

    float4 ra[4];
    uint4  rb[2];

    auto load_regs = [&](int c) {
#pragma unroll
        for (int p = 0; p < 4; p++)
            ra[p] = *(const float4*)&X[(size_t)(m0 + a_row + 32 * p) * D + c * 32 + a_c4];
#pragma unroll
        for (int p = 0; p < 2; p++)
            rb[p] = *(const uint4*)&W[(size_t)(c * 32 + b_kk + 16 * p) * D + n0 + b_n8];
    };
    auto store_smem = [&](int buf) {
        __half* a_s = smh + buf * STG;
        __half* b_s = a_s + ASZ;
#pragma unroll
        for (int p = 0; p < 4; p++) {
            __half2 h0 = __floats2half2_rn(ra[p].x, ra[p].y);
            __half2 h1 = __floats2half2_rn(ra[p].z, ra[p].w);
            *(__half2*)&a_s[(a_row + 32 * p) * A_LD + a_c4]     = h0;
            *(__half2*)&a_s[(a_row + 32 * p) * A_LD + a_c4 + 2] = h1;
        }
#pragma unroll
        for (int p = 0; p < 2; p++)
            *(uint4*)&b_s[(b_kk + 16 * p) * B_LD + b_n8] = rb[p];
    };

    wmma::fragment<wmma::accumulator, 16, 16, 16, float> cf[4][2];
#pragma unroll
    for (int i = 0; i < 4; i++)
#pragma unroll
        for (int j = 0; j < 2; j++) wmma::fill_fragment(cf[i][j], 0.0f);

    load_regs(0);
    store_smem(0);
    __syncthreads();

    for (int c = 0; c < 8; c++) {
        if (c < 7) load_regs(c + 1);

        const int buf = c & 1;
        const __half* a_s = smh + buf * STG;
        const __half* b_s = a_s + ASZ;
#pragma unroll
        for (int ks = 0; ks < 2; ks++) {
            wmma::fragment<wmma::matrix_a, 16, 16, 16, __half, wmma::row_major> af[4];
            wmma::fragment<wmma::matrix_b, 16, 16, 16, __half, wmma::row_major> bf[2];
#pragma unroll
            for (int i = 0; i < 4; i++)
                wmma::load_matrix_sync(af[i], a_s + (wm * 64 + 16 * i) * A_LD + ks * 16, A_LD);
#pragma unroll
            for (int j = 0; j < 2; j++)
                wmma::load_matrix_sync(bf[j], b_s + (ks * 16) * B_LD + wn * 32 + 16 * j, B_LD);
#pragma unroll
            for (int i = 0; i < 4; i++)
#pragma unroll
                for (int j = 0; j < 2; j++)
                    wmma::mma_sync(cf[i][j], af[i], bf[j], cf[i][j]);
        }

        if (c < 7) store_smem((c + 1) & 1);
        __syncthreads();
    }

    // Epilogue -> packed scratch
    float* stg = reinterpret_cast<float*>(smh) + wid * (16 * 20);
    const int er = lane >> 1;
    const int ec = (lane & 1) * 8;
#pragma unroll
    for (int i = 0; i < 4; i++) {
#pragma unroll
        for (int j = 0; j < 2; j++) {
            wmma::store_matrix_sync(stg, cf[i][j], 20, wmma::mem_row_major);
            __syncwarp();
            __half2 h[4];
#pragma unroll
            for (int t = 0; t < 4; t++)
                h[t] = __floats2half2_rn(stg[er * 20 + ec + 2 * t], stg[er * 20 + ec + 2 * t + 1]);
            const int brow = m0 + wm * 64 + 16 * i + er;
            *(uint4*)&C[(size_t)brow * BSTRIDE + n0 + wn * 32 + 16 * j + ec] = *(uint4*)&h[0];
            __syncwarp();
        }
    }
}

// ---------------------------------------------------------------------------
// Phase 2: per-batch attention. Round-10 base with ONE change: K-split
// logits over all 8 warps (8 K-steps per warp, 2 partial buffers) instead
// of 4 warps x 16 steps; parallel softmax sums the partials.
// smem 62464 B -> still 3 CTAs/SM.
// ---------------------------------------------------------------------------
#define QK_LD 264
#define LG_LD 36
#define P_LD  40
#define ATTN_SMEM_BYTES ((3 * 32 * QK_LD) * 2 + (2 * 32 * LG_LD) * 4 + (32 * P_LD) * 2)  // 62464

__global__ __launch_bounds__(256, 3) void attn_tc(float* __restrict__ out)
{
    extern __shared__ __align__(16) __half smem_h[];
    __half* qh = smem_h;
    __half* kh = qh + 32 * QK_LD;
    __half* vh = kh + 32 * QK_LD;
    float*  lg = (float*)(vh + 32 * QK_LD);      // 2 x 32 x LG_LD
    __half* ph = (__half*)(lg + 2 * 32 * LG_LD);

    const int b   = blockIdx.x;
    const int tid = threadIdx.x;
    const int wid = tid >> 5;
    const uint32_t sb0 = smem_u32(qh);
    const __half* src = g_scr + (size_t)b * BSTRIDE;

#pragma unroll
    for (int p = 0; p < 12; p++) {
        const int idx = p * 256 + tid;
        const int t   = idx >> 10;
        const int rem = idx & 1023;
        const int n   = rem >> 5;
        const int a8  = (rem & 31) * 8;
        const uint32_t dst = sb0 + (t * 32 * QK_LD + n * QK_LD + a8) * 2;
        CP_ASYNC16(dst, src + idx * 8);
    }
    CP_COMMIT();
    CP_WAIT0();
    __syncthreads();

    // Logits: 8 warps, K-split (khalf) x 2x2 tile grid; 8 K-steps per warp
    {
        const int khalf = wid >> 2;
        const int nt = (wid >> 1) & 1;
        const int mt = wid & 1;
        wmma::fragment<wmma::accumulator, 16, 16, 16, float> acc;
        wmma::fill_fragment(acc, 0.0f);
#pragma unroll
        for (int ks = 0; ks < 8; ks++) {
            const int k0 = khalf * 128 + ks * 16;
            wmma::fragment<wmma::matrix_a, 16, 16, 16, __half, wmma::row_major> af;
            wmma::fragment<wmma::matrix_b, 16, 16, 16, __half, wmma::col_major> bf;
            wmma::load_matrix_sync(af, qh + (nt * 16) * QK_LD + k0, QK_LD);
            wmma::load_matrix_sync(bf, kh + (mt * 16) * QK_LD + k0, QK_LD);
            wmma::mma_sync(acc, af, bf, acc);
        }
        wmma::store_matrix_sync(lg + khalf * 32 * LG_LD + (nt * 16) * LG_LD + mt * 16,
                                acc, LG_LD, wmma::mem_row_major);
    }
    __syncthreads();

    // Softmax: 32 rows x 8 lanes x 4 cols; sum K-split partials; shfl reduce
    {
        const int row = tid >> 3;
        const int c0  = (tid & 7) * 4;
        const float* l0 = lg + row * LG_LD + c0;
        const float* l1 = l0 + 32 * LG_LD;
        float x0 = l0[0] + l1[0];
        float x1 = l0[1] + l1[1];
        float x2 = l0[2] + l1[2];
        float x3 = l0[3] + l1[3];
        float mx = fmaxf(fmaxf(x0, x1), fmaxf(x2, x3));
#pragma unroll
        for (int d = 1; d < 8; d <<= 1)
            mx = fmaxf(mx, __shfl_xor_sync(0xffffffffu, mx, d));
        x0 = expf((x0 - mx) * 0.0625f);
        x1 = expf((x1 - mx) * 0.0625f);
        x2 = expf((x2 - mx) * 0.0625f);
        x3 = expf((x3 - mx) * 0.0625f);
        float s = x0 + x1 + x2 + x3;
#pragma unroll
        for (int d = 1; d < 8; d <<= 1)
            s += __shfl_xor_sync(0xffffffffu, s, d);
        const float inv = 1.0f / s;
        __half2 h0 = __floats2half2_rn(x0 * inv, x1 * inv);
        __half2 h1 = __floats2half2_rn(x2 * inv, x3 * inv);
        *(uint2*)&ph[row * P_LD + c0] = make_uint2(*(uint32_t*)&h0, *(uint32_t*)&h1);
    }
    __syncthreads();

    // Output: out[n][b][o] = sum_m P[n][m] * vh[m][o]
    {
        const int mt2 = wid >> 2;
        const int oc  = wid & 3;
        wmma::fragment<wmma::accumulator, 16, 16, 16, float> acc[4];
#pragma unroll
        for (int j = 0; j < 4; j++) wmma::fill_fragment(acc[j], 0.0f);
#pragma unroll
        for (int ks = 0; ks < 2; ks++) {
            wmma::fragment<wmma::matrix_a, 16, 16, 16, __half, wmma::row_major> af;
            wmma::load_matrix_sync(af, ph + (mt2 * 16) * P_LD + ks * 16, P_LD);
#pragma unroll
            for (int j = 0; j < 4; j++) {
                wmma::fragment<wmma::matrix_b, 16, 16, 16, __half, wmma::row_major> bf;
                wmma::load_matrix_sync(bf, vh + (ks * 16) * QK_LD + oc * 64 + j * 16, QK_LD);
                wmma::mma_sync(acc[j], af, bf, acc[j]);
            }
        }
#pragma unroll
        for (int j = 0; j < 4; j++) {
            float* dst = out + (size_t)(mt2 * 16) * BS * D + (size_t)b * D + oc * 64 + j * 16;
            wmma::store_matrix_sync(dst, acc[j], (unsigned)(BS * D), wmma::mem_row_major);
        }
    }
}

// ---------------------------------------------------------------------------
extern "C" void kernel_launch(void* const* d_in, const int* in_sizes, int n_in,
                              void* d_out, int out_size)
{
    const float* q  = (const float*)d_in[0];
    const float* k  = (const float*)d_in[1];
    const float* qw = (const float*)d_in[2];
    const float* kw = (const float*)d_in[3];
    const float* vw = (const float*)d_in[4];
    float* out = (float*)d_out;

    (void)in_sizes; (void)n_in; (void)out_size;

    dim3 gw(16, 96);
    convert_w<<<gw, 256>>>(qw, kw, vw);

    cudaFuncSetAttribute(proj_wmma, cudaFuncAttributeMaxDynamicSharedMemorySize, PROJ_SMEM_BYTES);
    dim3 grid1(2, 32, 96);
    proj_wmma<<<grid1, 256, PROJ_SMEM_BYTES>>>(q, k);

    cudaFuncSetAttribute(attn_tc, cudaFuncAttributeMaxDynamicSharedMemorySize, ATTN_SMEM_BYTES);
    attn_tc<<<BS, 256, ATTN_SMEM_BYTES>>>(out);
}

// round 15
// speedup vs baseline: 1.1142x; 1.0034x over previous
#include <cuda_runtime.h>
#include <cuda_fp16.h>
#include <math.h>
#include <stdint.h>
#include <mma.h>

using namespace nvcuda;

#define BS    4096
#define NSLOT 32
#define D     256

// Packed fp16 scratch: [batch][tensor(q,k,v)][slot][dim]
#define BSTRIDE (3 * NSLOT * D)     // 24576 halfs per batch
__device__ __align__(16) __half g_scr[(size_t)BS * BSTRIDE];
__device__ __align__(16) __half g_wh [(size_t)96 * D * D];   // fp16 weights [gemm][k][n]

__device__ __forceinline__ uint32_t smem_u32(const void* p) {
    return (uint32_t)__cvta_generic_to_shared(p);
}
#define CP_ASYNC16(dst_u32, src_ptr) \
    asm volatile("cp.async.cg.shared.global [%0], [%1], 16;" :: "r"(dst_u32), "l"(src_ptr))
#define CP_COMMIT() asm volatile("cp.async.commit_group;" ::: "memory")
#define CP_WAIT0()  asm volatile("cp.async.wait_group 0;" ::: "memory")
#define CP_WAIT1()  asm volatile("cp.async.wait_group 1;" ::: "memory")

// ---------------------------------------------------------------------------
// Phase 0: weights fp32 -> fp16 in proj gemm order:
//   y < 32 -> qw[y];  y >= 32 -> s=(y-32)>>1, even->kw[s], odd->vw[s]
// ---------------------------------------------------------------------------
__global__ __launch_bounds__(256) void convert_w(
    const float* __restrict__ qw,
    const float* __restrict__ kw,
    const float* __restrict__ vw)
{
    const int y = blockIdx.y;
    const float* W;
    if (y < 32) W = qw + (size_t)y * D * D;
    else {
        const int s = (y - 32) >> 1;
        W = (((y - 32) & 1) == 0 ? kw : vw) + (size_t)s * D * D;
    }
    __half* dst = g_wh + (size_t)y * D * D;
    const int base = (blockIdx.x * 256 + threadIdx.x) * 4;
#pragma unroll
    for (int p = 0; p < 4; p++) {
        const int i = base + p * 16384;
        const float4 v = *(const float4*)&W[i];
        __half2 h0 = __floats2half2_rn(v.x, v.y);
        __half2 h1 = __floats2half2_rn(v.z, v.w);
        *(uint2*)&dst[i] = make_uint2(*(uint32_t*)&h0, *(uint32_t*)&h1);
    }
}

// ---------------------------------------------------------------------------
// Phase 1: 96 GEMMs C[4096,256] = X @ W, fp16 HMMA. (round-7/11 final form)
// grid (2,32,96), block 256 (8 warps 2m x 4n), tile 128x128, K-chunk 32,
// double-buffered, 2 CTAs/SM.
// ---------------------------------------------------------------------------
#define A_LD  40
#define B_LD  136
#define ASZ   (128 * A_LD)
#define BSZ   (32 * B_LD)
#define STG   (ASZ + BSZ)
#define PROJ_SMEM_BYTES (2 * STG * (int)sizeof(__half))   // 37888 B

__global__ __launch_bounds__(256, 2) void proj_wmma(
    const float* __restrict__ q,
    const float* __restrict__ k)
{
    extern __shared__ __align__(16) __half smh[];

    const int tid  = threadIdx.x;
    const int wid  = tid >> 5;
    const int lane = tid & 31;
    const int wm   = wid >> 2;
    const int wn   = wid & 3;
    const int n0   = blockIdx.x * 128;
    const int m0   = blockIdx.y * 128;
    const int y    = blockIdx.z;

    const float* X;
    int t_idx, s_idx;
    if (y < 32) { X = q + (size_t)y * BS * D; t_idx = 0; s_idx = y; }
    else {
        s_idx = (y - 32) >> 1;
        X = k + (size_t)s_idx * BS * D;
        t_idx = (((y - 32) & 1) == 0) ? 1 : 2;
    }
    __half* C = g_scr + (size_t)t_idx * (NSLOT * D) + (size_t)s_idx * D;
    const __half* W = g_wh + (size_t)y * D * D;

    const int a_row = tid >> 3;
    const int a_c4  = (tid & 7) * 4;
    const int b_kk  = tid >> 4;
    const int b_n8  = (tid & 15) * 8;

    float4 ra[4];
    uint4  rb[2];

    auto load_regs = [&](int c) {
#pragma unroll
        for (int p = 0; p < 4; p++)
            ra[p] = *(const float4*)&X[(size_t)(m0 + a_row + 32 * p) * D + c * 32 + a_c4];
#pragma unroll
        for (int p = 0; p < 2; p++)
            rb[p] = *(const uint4*)&W[(size_t)(c * 32 + b_kk + 16 * p) * D + n0 + b_n8];
    };
    auto store_smem = [&](int buf) {
        __half* a_s = smh + buf * STG;
        __half* b_s = a_s + ASZ;
#pragma unroll
        for (int p = 0; p < 4; p++) {
            __half2 h0 = __floats2half2_rn(ra[p].x, ra[p].y);
            __half2 h1 = __floats2half2_rn(ra[p].z, ra[p].w);
            *(__half2*)&a_s[(a_row + 32 * p) * A_LD + a_c4]     = h0;
            *(__half2*)&a_s[(a_row + 32 * p) * A_LD + a_c4 + 2] = h1;
        }
#pragma unroll
        for (int p = 0; p < 2; p++)
            *(uint4*)&b_s[(b_kk + 16 * p) * B_LD + b_n8] = rb[p];
    };

    wmma::fragment<wmma::accumulator, 16, 16, 16, float> cf[4][2];
#pragma unroll
    for (int i = 0; i < 4; i++)
#pragma unroll
        for (int j = 0; j < 2; j++) wmma::fill_fragment(cf[i][j], 0.0f);

    load_regs(0);
    store_smem(0);
    __syncthreads();

    for (int c = 0; c < 8; c++) {
        if (c < 7) load_regs(c + 1);

        const int buf = c & 1;
        const __half* a_s = smh + buf * STG;
        const __half* b_s = a_s + ASZ;
#pragma unroll
        for (int ks = 0; ks < 2; ks++) {
            wmma::fragment<wmma::matrix_a, 16, 16, 16, __half, wmma::row_major> af[4];
            wmma::fragment<wmma::matrix_b, 16, 16, 16, __half, wmma::row_major> bf[2];
#pragma unroll
            for (int i = 0; i < 4; i++)
                wmma::load_matrix_sync(af[i], a_s + (wm * 64 + 16 * i) * A_LD + ks * 16, A_LD);
#pragma unroll
            for (int j = 0; j < 2; j++)
                wmma::load_matrix_sync(bf[j], b_s + (ks * 16) * B_LD + wn * 32 + 16 * j, B_LD);
#pragma unroll
            for (int i = 0; i < 4; i++)
#pragma unroll
                for (int j = 0; j < 2; j++)
                    wmma::mma_sync(cf[i][j], af[i], bf[j], cf[i][j]);
        }

        if (c < 7) store_smem((c + 1) & 1);
        __syncthreads();
    }

    // Epilogue -> packed scratch
    float* stg = reinterpret_cast<float*>(smh) + wid * (16 * 20);
    const int er = lane >> 1;
    const int ec = (lane & 1) * 8;
#pragma unroll
    for (int i = 0; i < 4; i++) {
#pragma unroll
        for (int j = 0; j < 2; j++) {
            wmma::store_matrix_sync(stg, cf[i][j], 20, wmma::mem_row_major);
            __syncwarp();
            __half2 h[4];
#pragma unroll
            for (int t = 0; t < 4; t++)
                h[t] = __floats2half2_rn(stg[er * 20 + ec + 2 * t], stg[er * 20 + ec + 2 * t + 1]);
            const int brow = m0 + wm * 64 + 16 * i + er;
            *(uint4*)&C[(size_t)brow * BSTRIDE + n0 + wn * 32 + 16 * j + ec] = *(uint4*)&h[0];
            __syncwarp();
        }
    }
}

// ---------------------------------------------------------------------------
// Phase 2: per-batch attention (round-10/11 form). ONE change: staging split
// into two cp.async groups — (q,k) waited before logits, v drained under
// logits+softmax and waited only before the output phase.
// ---------------------------------------------------------------------------
#define QK_LD 264
#define LG_LD 36
#define P_LD  40
#define ATTN_SMEM_BYTES ((3 * 32 * QK_LD) * 2 + (32 * LG_LD) * 4 + (32 * P_LD) * 2)  // 57856

__global__ __launch_bounds__(256, 4) void attn_tc(float* __restrict__ out)
{
    extern __shared__ __align__(16) __half smem_h[];
    __half* qh = smem_h;
    __half* kh = qh + 32 * QK_LD;
    __half* vh = kh + 32 * QK_LD;
    float*  lg = (float*)(vh + 32 * QK_LD);
    __half* ph = (__half*)(lg + 32 * LG_LD);

    const int b   = blockIdx.x;
    const int tid = threadIdx.x;
    const int wid = tid >> 5;
    const uint32_t sb0 = smem_u32(qh);
    const __half* src = g_scr + (size_t)b * BSTRIDE;

    // Group 0: q + k (p = 0..7); Group 1: v (p = 8..11)
#pragma unroll
    for (int p = 0; p < 8; p++) {
        const int idx = p * 256 + tid;
        const int t   = idx >> 10;
        const int rem = idx & 1023;
        const int n   = rem >> 5;
        const int a8  = (rem & 31) * 8;
        const uint32_t dst = sb0 + (t * 32 * QK_LD + n * QK_LD + a8) * 2;
        CP_ASYNC16(dst, src + idx * 8);
    }
    CP_COMMIT();
#pragma unroll
    for (int p = 8; p < 12; p++) {
        const int idx = p * 256 + tid;
        const int rem = idx & 1023;
        const int n   = rem >> 5;
        const int a8  = (rem & 31) * 8;
        const uint32_t dst = sb0 + (2 * 32 * QK_LD + n * QK_LD + a8) * 2;
        CP_ASYNC16(dst, src + idx * 8);
    }
    CP_COMMIT();

    CP_WAIT1();              // q,k complete; v may still be in flight
    __syncthreads();

    // Logits: 4 warps, each a 16x16 tile over full K=256
    if (wid < 4) {
        const int nt = wid >> 1;
        const int mt = wid & 1;
        wmma::fragment<wmma::accumulator, 16, 16, 16, float> acc;
        wmma::fill_fragment(acc, 0.0f);
#pragma unroll
        for (int ks = 0; ks < 16; ks++) {
            wmma::fragment<wmma::matrix_a, 16, 16, 16, __half, wmma::row_major> af;
            wmma::fragment<wmma::matrix_b, 16, 16, 16, __half, wmma::col_major> bf;
            wmma::load_matrix_sync(af, qh + (nt * 16) * QK_LD + ks * 16, QK_LD);
            wmma::load_matrix_sync(bf, kh + (mt * 16) * QK_LD + ks * 16, QK_LD);
            wmma::mma_sync(acc, af, bf, acc);
        }
        wmma::store_matrix_sync(lg + (nt * 16) * LG_LD + mt * 16, acc, LG_LD,
                                wmma::mem_row_major);
    }
    __syncthreads();

    // Softmax: 32 rows x 8 lanes x 4 cols; shfl reductions in 8-lane groups
    {
        const int row = tid >> 3;
        const int c0  = (tid & 7) * 4;
        float x0 = lg[row * LG_LD + c0 + 0];
        float x1 = lg[row * LG_LD + c0 + 1];
        float x2 = lg[row * LG_LD + c0 + 2];
        float x3 = lg[row * LG_LD + c0 + 3];
        float mx = fmaxf(fmaxf(x0, x1), fmaxf(x2, x3));
#pragma unroll
        for (int d = 1; d < 8; d <<= 1)
            mx = fmaxf(mx, __shfl_xor_sync(0xffffffffu, mx, d));
        x0 = expf((x0 - mx) * 0.0625f);
        x1 = expf((x1 - mx) * 0.0625f);
        x2 = expf((x2 - mx) * 0.0625f);
        x3 = expf((x3 - mx) * 0.0625f);
        float s = x0 + x1 + x2 + x3;
#pragma unroll
        for (int d = 1; d < 8; d <<= 1)
            s += __shfl_xor_sync(0xffffffffu, s, d);
        const float inv = 1.0f / s;
        __half2 h0 = __floats2half2_rn(x0 * inv, x1 * inv);
        __half2 h1 = __floats2half2_rn(x2 * inv, x3 * inv);
        *(uint2*)&ph[row * P_LD + c0] = make_uint2(*(uint32_t*)&h0, *(uint32_t*)&h1);
    }
    CP_WAIT0();              // v complete (hidden under logits+softmax)
    __syncthreads();

    // Output: out[n][b][o] = sum_m P[n][m] * vh[m][o]
    {
        const int mt2 = wid >> 2;
        const int oc  = wid & 3;
        wmma::fragment<wmma::accumulator, 16, 16, 16, float> acc[4];
#pragma unroll
        for (int j = 0; j < 4; j++) wmma::fill_fragment(acc[j], 0.0f);
#pragma unroll
        for (int ks = 0; ks < 2; ks++) {
            wmma::fragment<wmma::matrix_a, 16, 16, 16, __half, wmma::row_major> af;
            wmma::load_matrix_sync(af, ph + (mt2 * 16) * P_LD + ks * 16, P_LD);
#pragma unroll
            for (int j = 0; j < 4; j++) {
                wmma::fragment<wmma::matrix_b, 16, 16, 16, __half, wmma::row_major> bf;
                wmma::load_matrix_sync(bf, vh + (ks * 16) * QK_LD + oc * 64 + j * 16, QK_LD);
                wmma::mma_sync(acc[j], af, bf, acc[j]);
            }
        }
#pragma unroll
        for (int j = 0; j < 4; j++) {
            float* dst = out + (size_t)(mt2 * 16) * BS * D + (size_t)b * D + oc * 64 + j * 16;
            wmma::store_matrix_sync(dst, acc[j], (unsigned)(BS * D), wmma::mem_row_major);
        }
    }
}

// ---------------------------------------------------------------------------
extern "C" void kernel_launch(void* const* d_in, const int* in_sizes, int n_in,
                              void* d_out, int out_size)
{
    const float* q  = (const float*)d_in[0];
    const float* k  = (const float*)d_in[1];
    const float* qw = (const float*)d_in[2];
    const float* kw = (const float*)d_in[3];
    const float* vw = (const float*)d_in[4];
    float* out = (float*)d_out;

    (void)in_sizes; (void)n_in; (void)out_size;

    dim3 gw(16, 96);
    convert_w<<<gw, 256>>>(qw, kw, vw);

    cudaFuncSetAttribute(proj_wmma, cudaFuncAttributeMaxDynamicSharedMemorySize, PROJ_SMEM_BYTES);
    dim3 grid1(2, 32, 96);
    proj_wmma<<<grid1, 256, PROJ_SMEM_BYTES>>>(q, k);

    cudaFuncSetAttribute(attn_tc, cudaFuncAttributeMaxDynamicSharedMemorySize, ATTN_SMEM_BYTES);
    attn_tc<<<BS, 256, ATTN_SMEM_BYTES>>>(out);
}